// round 14
// baseline (speedup 1.0000x reference)
#include <cuda_runtime.h>
#include <cuda_bf16.h>
#include <math.h>
#include <stdint.h>

#define S_LEN   2048
#define HID_DIM 3584
#define NH      16
#define NKV     8
#define HD      256
#define QKV_N   ((NH + 2 * NKV) * HD)   // 8192
#define ATTN_N  (NH * HD)               // 4096
#define WIN     1024
#define SOFTCAP 50.0f
#define SCALING 0.0625f

// ---------------- scratch (__device__ globals; no allocs allowed) ----------
__device__ __align__(256) __nv_bfloat16 g_Ah[S_LEN * 4096];
__device__ __align__(256) __nv_bfloat16 g_Al[S_LEN * 4096];
__device__ __align__(256) __nv_bfloat16 g_Bh[8192 * 3584];
__device__ __align__(256) __nv_bfloat16 g_Bl[8192 * 3584];
// per-head bf16 planes. Q/K planes hold PERMUTED dims (2j <- j, 2j+1 <- j+128)
__device__ __align__(256) __nv_bfloat16 g_Qh[NH  * S_LEN * HD];
__device__ __align__(256) __nv_bfloat16 g_Ql[NH  * S_LEN * HD];
__device__ __align__(256) __nv_bfloat16 g_Kh[NKV * S_LEN * HD];
__device__ __align__(256) __nv_bfloat16 g_Kl[NKV * S_LEN * HD];
__device__ __align__(256) __nv_bfloat16 g_Vh[NKV * S_LEN * HD];
__device__ __align__(256) __nv_bfloat16 g_Vl[NKV * S_LEN * HD];

// ---------------- PTX helpers ----------------------------------------------
__device__ __forceinline__ uint32_t smem_u32(const void* p) {
    uint32_t a;
    asm("{ .reg .u64 t; cvta.to.shared.u64 t, %1; cvt.u32.u64 %0, t; }" : "=r"(a) : "l"(p));
    return a;
}
#define CP_ASYNC16(dst, src) \
    asm volatile("cp.async.cg.shared.global [%0], [%1], 16;" :: "r"(dst), "l"(src) : "memory")
#define CP_COMMIT() asm volatile("cp.async.commit_group;" ::: "memory")
#define CP_WAIT1()  asm volatile("cp.async.wait_group 1;" ::: "memory")

#define LDSM_X4(r0, r1, r2, r3, addr) \
    asm volatile("ldmatrix.sync.aligned.m8n8.x4.shared.b16 {%0,%1,%2,%3}, [%4];" \
        : "=r"(r0), "=r"(r1), "=r"(r2), "=r"(r3) : "r"(addr))
#define LDSM_X4T(r0, r1, r2, r3, addr) \
    asm volatile("ldmatrix.sync.aligned.m8n8.x4.trans.shared.b16 {%0,%1,%2,%3}, [%4];" \
        : "=r"(r0), "=r"(r1), "=r"(r2), "=r"(r3) : "r"(addr))

#define MMA_BF16(d, a, b0, b1) \
    asm volatile("mma.sync.aligned.m16n8k16.row.col.f32.bf16.bf16.f32 " \
        "{%0,%1,%2,%3}, {%4,%5,%6,%7}, {%8,%9}, {%0,%1,%2,%3};" \
        : "+f"((d)[0]), "+f"((d)[1]), "+f"((d)[2]), "+f"((d)[3]) \
        : "r"((a)[0]), "r"((a)[1]), "r"((a)[2]), "r"((a)[3]), "r"(b0), "r"(b1))

__device__ __forceinline__ void split_bf16(float x, __nv_bfloat16& h, __nv_bfloat16& l) {
    h = __float2bfloat16_rn(x);
    l = __float2bfloat16_rn(x - __bfloat162float(h));
}
__device__ __forceinline__ void split2(float a, float b, uint32_t& hi, uint32_t& lo) {
    __nv_bfloat16 ha, la, hb, lb;
    split_bf16(a, ha, la); split_bf16(b, hb, lb);
    __nv_bfloat162 H; H.x = ha; H.y = hb;
    __nv_bfloat162 L; L.x = la; L.y = lb;
    hi = *reinterpret_cast<uint32_t*>(&H);
    lo = *reinterpret_cast<uint32_t*>(&L);
}

// ---------------------------------------------------------------------------
// conv_split (hidden/A and Wo)
// ---------------------------------------------------------------------------
__global__ void conv_split(const float4* __restrict__ X, __nv_bfloat162* __restrict__ H,
                           __nv_bfloat162* __restrict__ L)
{
    const size_t i = (size_t)blockIdx.x * blockDim.x + threadIdx.x;
    float4 v = X[i];
    __nv_bfloat16 h0, l0, h1, l1, h2, l2, h3, l3;
    split_bf16(v.x, h0, l0); split_bf16(v.y, h1, l1);
    split_bf16(v.z, h2, l2); split_bf16(v.w, h3, l3);
    __nv_bfloat162 a, b, c, d;
    a.x = h0; a.y = h1;  b.x = h2; b.y = h3;
    c.x = l0; c.y = l1;  d.x = l2; d.y = l3;
    H[2 * i] = a; H[2 * i + 1] = b;
    L[2 * i] = c; L[2 * i + 1] = d;
}

// ---------------------------------------------------------------------------
// convB_qkv: permuted QKV weight conversion (rope pairs adjacent)
// ---------------------------------------------------------------------------
__global__ void convB_qkv(const float* __restrict__ W)
{
    const size_t idx = (size_t)blockIdx.x * 256 + threadIdx.x;
    const int k = (int)(idx >> 12);
    const int c = (int)((idx & 4095) << 1);
    const int head = c >> 8;
    const int dn   = c & 255;
    float w1, w2;
    const float* rowp = W + (size_t)k * QKV_N;
    if (head < NH + NKV) {
        const int j = dn >> 1;
        w1 = rowp[head * 256 + j];
        w2 = rowp[head * 256 + j + 128];
    } else {
        w1 = rowp[c];
        w2 = rowp[c + 1];
    }
    uint32_t hi, lo;
    split2(w1, w2, hi, lo);
    const size_t o = (size_t)k * QKV_N + c;
    *reinterpret_cast<uint32_t*>(&g_Bh[o]) = hi;
    *reinterpret_cast<uint32_t*>(&g_Bl[o]) = lo;
}

// ---------------------------------------------------------------------------
// Fused epilogue store for the QKV GEMM (rope in-register, split to planes)
// ---------------------------------------------------------------------------
__device__ __forceinline__ void qkv_store(int row, int col, float x1, float x2,
                                          const float* __restrict__ fcos,
                                          const float* __restrict__ fsin)
{
    const int head = col >> 8;
    const int dn   = col & 255;
    uint32_t hi, lo;
    if (head < NH + NKV) {
        const int j = dn >> 1;
        const float cv = fcos[(size_t)row * 128 + j];
        const float sv = fsin[(size_t)row * 128 + j];
        float y1 = x1 * cv - x2 * sv;
        float y2 = x1 * sv + x2 * cv;
        if (head < NH) {
            y1 *= SCALING; y2 *= SCALING;
            split2(y1, y2, hi, lo);
            const size_t o = ((size_t)head * S_LEN + row) * HD + dn;
            *reinterpret_cast<uint32_t*>(&g_Qh[o]) = hi;
            *reinterpret_cast<uint32_t*>(&g_Ql[o]) = lo;
        } else {
            split2(y1, y2, hi, lo);
            const size_t o = ((size_t)(head - NH) * S_LEN + row) * HD + dn;
            *reinterpret_cast<uint32_t*>(&g_Kh[o]) = hi;
            *reinterpret_cast<uint32_t*>(&g_Kl[o]) = lo;
        }
    } else {
        split2(x1, x2, hi, lo);
        const size_t o = ((size_t)(head - NH - NKV) * S_LEN + row) * HD + dn;
        *reinterpret_cast<uint32_t*>(&g_Vh[o]) = hi;
        *reinterpret_cast<uint32_t*>(&g_Vl[o]) = lo;
    }
}

// ---------------------------------------------------------------------------
// HMMA split-bf16 GEMM (R12/R13 proven single-barrier 3-stage pipeline)
// ---------------------------------------------------------------------------
#define BM   128
#define BN   128
#define BK   32
#define LDA  40
#define LDB  136
#define TILE_A_B (128 * LDA * 2)
#define TILE_B_B (32 * LDB * 2)
#define OFF_AH   0
#define OFF_AL   (TILE_A_B)
#define OFF_BH   (2 * TILE_A_B)
#define OFF_BL   (2 * TILE_A_B + TILE_B_B)
#define STAGE_B  (2 * TILE_A_B + 2 * TILE_B_B)
#define NSTG 3

template <bool FUSE_ROPE>
__global__ void __launch_bounds__(256, 2)
gemm_mma(const __nv_bfloat16* __restrict__ Ah, const __nv_bfloat16* __restrict__ Al,
         const __nv_bfloat16* __restrict__ Bh, const __nv_bfloat16* __restrict__ Bl,
         float* __restrict__ C, int N, int K,
         const float* __restrict__ fcos, const float* __restrict__ fsin)
{
    extern __shared__ char smbuf[];
    const uint32_t sb = smem_u32(smbuf);

    const int tid  = threadIdx.x;
    const int lane = tid & 31;
    const int wid  = tid >> 5;
    const int wm   = (wid & 3) * 32;
    const int wn   = (wid >> 2) * 64;
    const int nb   = blockIdx.x, mbk = blockIdx.y;
    const int m0   = mbk * BM, n0 = nb * BN;
    const int KT   = K / BK;

    const int ar = tid >> 1, ac = (tid & 1) * 16;
    const int br = tid >> 3, bc = (tid & 7) * 16;

    const __nv_bfloat16* gAh = Ah + (size_t)(m0 + ar) * K + ac;
    const __nv_bfloat16* gAl = Al + (size_t)(m0 + ar) * K + ac;
    const __nv_bfloat16* gBh = Bh + (size_t)br * N + n0 + bc;
    const __nv_bfloat16* gBl = Bl + (size_t)br * N + n0 + bc;

    auto load_stage = [&](int s, int c) {
        const uint32_t st = sb + s * STAGE_B;
        const size_t ka = (size_t)c * BK;
        const uint32_t sa = st + (ar * LDA + ac) * 2;
        CP_ASYNC16(sa + OFF_AH,      gAh + ka);
        CP_ASYNC16(sa + OFF_AH + 16, gAh + ka + 8);
        CP_ASYNC16(sa + OFF_AL,      gAl + ka);
        CP_ASYNC16(sa + OFF_AL + 16, gAl + ka + 8);
        const uint32_t sbm = st + (br * LDB + bc) * 2;
        const size_t kb = (size_t)c * BK * N;
        CP_ASYNC16(sbm + OFF_BH,      gBh + kb);
        CP_ASYNC16(sbm + OFF_BH + 16, gBh + kb + 8);
        CP_ASYNC16(sbm + OFF_BL,      gBl + kb);
        CP_ASYNC16(sbm + OFF_BL + 16, gBl + kb + 8);
    };

    load_stage(0, 0); CP_COMMIT();
    load_stage(1, 1); CP_COMMIT();

    float d[2][8][4];
    #pragma unroll
    for (int i = 0; i < 2; i++)
        #pragma unroll
        for (int j = 0; j < 8; j++)
            #pragma unroll
            for (int r = 0; r < 4; r++) d[i][j][r] = 0.f;

    const int lrow = lane & 15;
    const int lcol = (lane >> 4) * 8;

    for (int c = 0; c < KT; c++) {
        CP_WAIT1();
        __syncthreads();
        const int c2 = c + 2;
        if (c2 < KT) load_stage(c2 % NSTG, c2);
        CP_COMMIT();

        const uint32_t st = sb + (c % NSTG) * STAGE_B;

        #pragma unroll
        for (int ks = 0; ks < 2; ks++) {
            uint32_t ah[2][4], al[2][4];
            #pragma unroll
            for (int mb = 0; mb < 2; mb++) {
                const uint32_t aoff = st + ((wm + mb * 16 + lrow) * LDA + ks * 16 + lcol) * 2;
                LDSM_X4(ah[mb][0], ah[mb][1], ah[mb][2], ah[mb][3], aoff + OFF_AH);
                LDSM_X4(al[mb][0], al[mb][1], al[mb][2], al[mb][3], aoff + OFF_AL);
            }
            uint32_t bh[4][4], bl[4][4];
            #pragma unroll
            for (int ng = 0; ng < 4; ng++) {
                const uint32_t boff = st + ((ks * 16 + lrow) * LDB + wn + ng * 16 + lcol) * 2;
                LDSM_X4T(bh[ng][0], bh[ng][1], bh[ng][2], bh[ng][3], boff + OFF_BH);
                LDSM_X4T(bl[ng][0], bl[ng][1], bl[ng][2], bl[ng][3], boff + OFF_BL);
            }
            #pragma unroll
            for (int mb = 0; mb < 2; mb++) {
                #pragma unroll
                for (int ng = 0; ng < 4; ng++) {
                    MMA_BF16(d[mb][ng * 2 + 0], ah[mb], bh[ng][0], bh[ng][1]);
                    MMA_BF16(d[mb][ng * 2 + 1], ah[mb], bh[ng][2], bh[ng][3]);
                    MMA_BF16(d[mb][ng * 2 + 0], ah[mb], bl[ng][0], bl[ng][1]);
                    MMA_BF16(d[mb][ng * 2 + 1], ah[mb], bl[ng][2], bl[ng][3]);
                    MMA_BF16(d[mb][ng * 2 + 0], al[mb], bh[ng][0], bh[ng][1]);
                    MMA_BF16(d[mb][ng * 2 + 1], al[mb], bh[ng][2], bh[ng][3]);
                }
            }
        }
    }

    #pragma unroll
    for (int mb = 0; mb < 2; mb++) {
        const int row = m0 + wm + mb * 16 + (lane >> 2);
        #pragma unroll
        for (int nb8 = 0; nb8 < 8; nb8++) {
            const int col = n0 + wn + nb8 * 8 + (lane & 3) * 2;
            if (FUSE_ROPE) {
                qkv_store(row,     col, d[mb][nb8][0], d[mb][nb8][1], fcos, fsin);
                qkv_store(row + 8, col, d[mb][nb8][2], d[mb][nb8][3], fcos, fsin);
            } else {
                float2 v0 = make_float2(d[mb][nb8][0], d[mb][nb8][1]);
                float2 v1 = make_float2(d[mb][nb8][2], d[mb][nb8][3]);
                *reinterpret_cast<float2*>(C + (size_t)row * N + col) = v0;
                *reinterpret_cast<float2*>(C + (size_t)(row + 8) * N + col) = v1;
            }
        }
    }
}

// ---------------------------------------------------------------------------
// Tensor-core flash attention, 16 warps (512 threads):
//   wq = wid>>2 (4 q-groups x 16 rows), kg = (wid>>1)&1 (k-half),
//   dg = wid&1 (d-half for PV; QK duplicated across dg).
// o[16][4] = 64 accumulator regs -> fits 128-reg cap, 4 warps/SMSP.
// ---------------------------------------------------------------------------
#define SROWB 528
#define QPLANE (64 * SROWB)
#define KVPLANE (32 * SROWB)
#define KVSTAGE (4 * KVPLANE)
#define ATTN_SMEM (2 * QPLANE + 2 * KVSTAGE + 256)

__global__ void __launch_bounds__(512, 1) attn_mma_kernel()
{
    extern __shared__ char smv[];
    const uint32_t sb = smem_u32(smv);
    const uint32_t QH = sb, QL = sb + QPLANE, ST0 = sb + 2 * QPLANE;
    float* sSum = reinterpret_cast<float*>(smv + 2 * QPLANE + 2 * KVSTAGE);

    const int tid  = threadIdx.x;
    const int lane = tid & 31;
    const int wid  = tid >> 5;
    const int wq   = wid >> 2;        // 0..3: 16 q rows each
    const int kg   = (wid >> 1) & 1;  // k-half of 32-k chunk
    const int dg   = wid & 1;         // d-half (PV only)
    const int q0   = blockIdx.x * 64;
    const int h    = blockIdx.y;
    const int kvh  = h >> 1;

    const int lrow  = lane & 15;
    const int lcolb = (lane >> 4) * 16;
    const int g     = lane >> 2;
    const int t2    = (lane & 3) * 2;

    if (tid < 64) sSum[tid] = 0.f;

    const __nv_bfloat16* pQh = g_Qh + ((size_t)h * S_LEN + q0) * HD;
    const __nv_bfloat16* pQl = g_Ql + ((size_t)h * S_LEN + q0) * HD;
    const __nv_bfloat16* bKh = g_Kh + (size_t)kvh * S_LEN * HD;
    const __nv_bfloat16* bKl = g_Kl + (size_t)kvh * S_LEN * HD;
    const __nv_bfloat16* bVh = g_Vh + (size_t)kvh * S_LEN * HD;
    const __nv_bfloat16* bVl = g_Vl + (size_t)kvh * S_LEN * HD;

    for (int i = tid; i < 64 * 32; i += 512) {
        const int r = i >> 5, ch = i & 31;
        const uint32_t o = (uint32_t)r * SROWB + ch * 16;
        const size_t go = (size_t)r * HD + ch * 8;
        CP_ASYNC16(QH + o, pQh + go);
        CP_ASYNC16(QL + o, pQl + go);
    }

    auto load_kv = [&](int s, int kb) {
        const uint32_t base = ST0 + s * KVSTAGE;
        for (int i = tid; i < 32 * 32; i += 512) {
            const int r = i >> 5, ch = i & 31;
            const uint32_t o = (uint32_t)r * SROWB + ch * 16;
            const size_t go = (size_t)(kb + r) * HD + ch * 8;
            CP_ASYNC16(base + o,               bKh + go);
            CP_ASYNC16(base + KVPLANE + o,     bKl + go);
            CP_ASYNC16(base + 2 * KVPLANE + o, bVh + go);
            CP_ASYNC16(base + 3 * KVPLANE + o, bVl + go);
        }
    };

    const int klo = (q0 - (WIN - 1)) > 0 ? (q0 - (WIN - 1)) : 0;
    const int kb0 = klo & ~31;
    const int nch = (q0 + 64 - kb0) >> 5;

    load_kv(0, kb0); CP_COMMIT();
    if (nch > 1) load_kv(1, kb0 + 32);
    CP_COMMIT();

    float o[16][4];
    #pragma unroll
    for (int i = 0; i < 16; i++)
        #pragma unroll
        for (int r = 0; r < 4; r++) o[i][r] = 0.f;
    float rs0 = 0.f, rs1 = 0.f;
    const int qrow0 = q0 + wq * 16 + g;

    for (int ic = 0; ic < nch; ic++) {
        const int kb = kb0 + ic * 32;
        CP_WAIT1();
        __syncthreads();
        const uint32_t st = ST0 + (ic & 1) * KVSTAGE;

        // ---- S = Q K^T for this warp's 16-k half (duplicated across dg) ----
        float sf[2][4];
        #pragma unroll
        for (int t = 0; t < 2; t++)
            #pragma unroll
            for (int r = 0; r < 4; r++) sf[t][r] = 0.f;

        #pragma unroll
        for (int dc = 0; dc < 16; dc++) {
            const uint32_t qa = QH + (uint32_t)(wq * 16 + lrow) * SROWB + dc * 32 + lcolb;
            uint32_t ah[4], al[4];
            LDSM_X4(ah[0], ah[1], ah[2], ah[3], qa);
            LDSM_X4(al[0], al[1], al[2], al[3], qa + QPLANE);
            const uint32_t ka = st + (uint32_t)(kg * 16 + lrow) * SROWB + dc * 32 + lcolb;
            uint32_t bh[4], bl[4];
            LDSM_X4(bh[0], bh[1], bh[2], bh[3], ka);
            LDSM_X4(bl[0], bl[1], bl[2], bl[3], ka + KVPLANE);
            MMA_BF16(sf[0], ah, bh[0], bh[2]);
            MMA_BF16(sf[1], ah, bh[1], bh[3]);
            MMA_BF16(sf[0], ah, bl[0], bl[2]);
            MMA_BF16(sf[1], ah, bl[1], bl[3]);
            MMA_BF16(sf[0], al, bh[0], bh[2]);
            MMA_BF16(sf[1], al, bh[1], bh[3]);
        }

        // ---- softcap + mask + exp(t-50) ----
        uint32_t ph[2][2], pl[2][2];
        #pragma unroll
        for (int t = 0; t < 2; t++) {
            const int kcol = kb + kg * 16 + t * 8 + t2;
            float pv[4];
            #pragma unroll
            for (int r = 0; r < 4; r++) {
                const int q = qrow0 + ((r >= 2) ? 8 : 0);
                const int k = kcol + (r & 1);
                const float u = __expf(0.04f * sf[t][r]);
                const float p = __expf(__fdividef(-100.f, u + 1.f));
                pv[r] = (k <= q && (q - k) < WIN) ? p : 0.f;
            }
            rs0 += pv[0] + pv[1];
            rs1 += pv[2] + pv[3];
            split2(pv[0], pv[1], ph[t][0], pl[t][0]);
            split2(pv[2], pv[3], ph[t][1], pl[t][1]);
        }

        // ---- O += P V over this warp's 16-k half, d-half dg ----
        uint32_t pah[4] = { ph[0][0], ph[0][1], ph[1][0], ph[1][1] };
        uint32_t pal[4] = { pl[0][0], pl[0][1], pl[1][0], pl[1][1] };
        #pragma unroll
        for (int dc = 0; dc < 8; dc++) {
            const uint32_t va = st + 2 * KVPLANE +
                (uint32_t)(kg * 16 + lrow) * SROWB + (dg * 8 + dc) * 32 + lcolb;
            uint32_t vh[4], vl[4];
            LDSM_X4T(vh[0], vh[1], vh[2], vh[3], va);
            LDSM_X4T(vl[0], vl[1], vl[2], vl[3], va + KVPLANE);
            MMA_BF16(o[dc * 2 + 0], pah, vh[0], vh[1]);
            MMA_BF16(o[dc * 2 + 1], pah, vh[2], vh[3]);
            MMA_BF16(o[dc * 2 + 0], pah, vl[0], vl[1]);
            MMA_BF16(o[dc * 2 + 1], pah, vl[2], vl[3]);
            MMA_BF16(o[dc * 2 + 0], pal, vh[0], vh[1]);
            MMA_BF16(o[dc * 2 + 1], pal, vh[2], vh[3]);
        }
        __syncthreads();
        if (ic + 2 < nch) load_kv(ic & 1, kb + 64);
        CP_COMMIT();
    }

    // ---- row sums: quad reduce; dg==0 warps (both kg) add to smem ----
    rs0 += __shfl_xor_sync(0xFFFFFFFFu, rs0, 1);
    rs0 += __shfl_xor_sync(0xFFFFFFFFu, rs0, 2);
    rs1 += __shfl_xor_sync(0xFFFFFFFFu, rs1, 1);
    rs1 += __shfl_xor_sync(0xFFFFFFFFu, rs1, 2);
    if (dg == 0 && (lane & 3) == 0) {
        atomicAdd(&sSum[wq * 16 + g], rs0);
        atomicAdd(&sSum[wq * 16 + g + 8], rs1);
    }

    // ---- O reduction across the kg pair via the dead KV stage ----
    float* red = reinterpret_cast<float*>(smv + 2 * QPLANE + (nch & 1) * KVSTAGE);
    if (kg == 1) {
        #pragma unroll
        for (int t = 0; t < 16; t++) {
            const int c  = dg * 128 + (t >> 1) * 16 + (t & 1) * 8 + t2;
            const int r0 = wq * 16 + g;
            *reinterpret_cast<float2*>(&red[(size_t)r0 * 256 + c])       = make_float2(o[t][0], o[t][1]);
            *reinterpret_cast<float2*>(&red[(size_t)(r0 + 8) * 256 + c]) = make_float2(o[t][2], o[t][3]);
        }
    }
    __syncthreads();
    if (kg == 0) {
        const float i0 = 1.0f / sSum[wq * 16 + g];
        const float i1 = 1.0f / sSum[wq * 16 + g + 8];
        const int row0 = q0 + wq * 16 + g;
        const int rl   = wq * 16 + g;
        #pragma unroll
        for (int t = 0; t < 16; t++) {
            const int c   = dg * 128 + (t >> 1) * 16 + (t & 1) * 8 + t2;
            const int col = h * HD + c;
            float2 p0 = *reinterpret_cast<float2*>(&red[(size_t)rl * 256 + c]);
            float2 p1 = *reinterpret_cast<float2*>(&red[(size_t)(rl + 8) * 256 + c]);
            uint32_t hi, lo;
            split2((o[t][0] + p0.x) * i0, (o[t][1] + p0.y) * i0, hi, lo);
            *reinterpret_cast<uint32_t*>(&g_Ah[(size_t)row0 * ATTN_N + col]) = hi;
            *reinterpret_cast<uint32_t*>(&g_Al[(size_t)row0 * ATTN_N + col]) = lo;
            split2((o[t][2] + p1.x) * i1, (o[t][3] + p1.y) * i1, hi, lo);
            *reinterpret_cast<uint32_t*>(&g_Ah[(size_t)(row0 + 8) * ATTN_N + col]) = hi;
            *reinterpret_cast<uint32_t*>(&g_Al[(size_t)(row0 + 8) * ATTN_N + col]) = lo;
        }
    }
}

// ---------------------------------------------------------------------------
extern "C" void kernel_launch(void* const* d_in, const int* in_sizes, int n_in,
                              void* d_out, int out_size)
{
    const float* hidden = (const float*)d_in[0];
    const float* Wqkv   = (const float*)d_in[1];
    const float* Wo     = (const float*)d_in[2];
    const float* fcos   = (const float*)d_in[3];
    const float* fsin   = (const float*)d_in[4];
    float* out = (float*)d_out;

    __nv_bfloat16 *Ah, *Al, *Bh, *Bl;
    cudaGetSymbolAddress((void**)&Ah, g_Ah);
    cudaGetSymbolAddress((void**)&Al, g_Al);
    cudaGetSymbolAddress((void**)&Bh, g_Bh);
    cudaGetSymbolAddress((void**)&Bl, g_Bl);

    const int gemm_smem = NSTG * STAGE_B;                 // 113664
    cudaFuncSetAttribute(gemm_mma<true>,  cudaFuncAttributeMaxDynamicSharedMemorySize, gemm_smem);
    cudaFuncSetAttribute(gemm_mma<false>, cudaFuncAttributeMaxDynamicSharedMemorySize, gemm_smem);
    cudaFuncSetAttribute(attn_mma_kernel, cudaFuncAttributeMaxDynamicSharedMemorySize, ATTN_SMEM);

    conv_split<<<(S_LEN * HID_DIM / 4) / 256, 256>>>(
        (const float4*)hidden, (__nv_bfloat162*)Ah, (__nv_bfloat162*)Al);
    convB_qkv<<<(HID_DIM * (QKV_N / 2)) / 256, 256>>>(Wqkv);

    gemm_mma<true><<<dim3(QKV_N / BN, S_LEN / BM), 256, gemm_smem>>>(
        Ah, Al, Bh, Bl, nullptr, QKV_N, HID_DIM, fcos, fsin);

    attn_mma_kernel<<<dim3(S_LEN / 64, NH), 512, ATTN_SMEM>>>();

    conv_split<<<((size_t)ATTN_N * HID_DIM / 4) / 256, 256>>>(
        (const float4*)Wo, (__nv_bfloat162*)Bh, (__nv_bfloat162*)Bl);
    gemm_mma<false><<<dim3(HID_DIM / BN, S_LEN / BM), 256, gemm_smem>>>(
        Ah, Al, Bh, Bl, out, HID_DIM, ATTN_N, nullptr, nullptr);
}

// round 15
// speedup vs baseline: 1.0661x; 1.0661x over previous
#include <cuda_runtime.h>
#include <cuda_bf16.h>
#include <math.h>
#include <stdint.h>

#define S_LEN   2048
#define HID_DIM 3584
#define NH      16
#define NKV     8
#define HD      256
#define QKV_N   ((NH + 2 * NKV) * HD)   // 8192
#define ATTN_N  (NH * HD)               // 4096
#define WIN     1024
#define SOFTCAP 50.0f
#define SCALING 0.0625f

// ---------------- scratch (__device__ globals; no allocs allowed) ----------
__device__ __align__(256) __nv_bfloat16 g_Ah[S_LEN * 4096];
__device__ __align__(256) __nv_bfloat16 g_Al[S_LEN * 4096];
__device__ __align__(256) __nv_bfloat16 g_Bh[8192 * 3584];
__device__ __align__(256) __nv_bfloat16 g_Bl[8192 * 3584];
// per-head bf16 planes. Q/K planes hold PERMUTED dims (2j <- j, 2j+1 <- j+128)
__device__ __align__(256) __nv_bfloat16 g_Qh[NH  * S_LEN * HD];
__device__ __align__(256) __nv_bfloat16 g_Ql[NH  * S_LEN * HD];
__device__ __align__(256) __nv_bfloat16 g_Kh[NKV * S_LEN * HD];
__device__ __align__(256) __nv_bfloat16 g_Kl[NKV * S_LEN * HD];
__device__ __align__(256) __nv_bfloat16 g_Vh[NKV * S_LEN * HD];
__device__ __align__(256) __nv_bfloat16 g_Vl[NKV * S_LEN * HD];

// ---------------- PTX helpers ----------------------------------------------
__device__ __forceinline__ uint32_t smem_u32(const void* p) {
    uint32_t a;
    asm("{ .reg .u64 t; cvta.to.shared.u64 t, %1; cvt.u32.u64 %0, t; }" : "=r"(a) : "l"(p));
    return a;
}
#define CP_ASYNC16(dst, src) \
    asm volatile("cp.async.cg.shared.global [%0], [%1], 16;" :: "r"(dst), "l"(src) : "memory")
#define CP_COMMIT() asm volatile("cp.async.commit_group;" ::: "memory")
#define CP_WAIT1()  asm volatile("cp.async.wait_group 1;" ::: "memory")

#define LDSM_X4(r0, r1, r2, r3, addr) \
    asm volatile("ldmatrix.sync.aligned.m8n8.x4.shared.b16 {%0,%1,%2,%3}, [%4];" \
        : "=r"(r0), "=r"(r1), "=r"(r2), "=r"(r3) : "r"(addr))
#define LDSM_X4T(r0, r1, r2, r3, addr) \
    asm volatile("ldmatrix.sync.aligned.m8n8.x4.trans.shared.b16 {%0,%1,%2,%3}, [%4];" \
        : "=r"(r0), "=r"(r1), "=r"(r2), "=r"(r3) : "r"(addr))

#define MMA_BF16(d, a, b0, b1) \
    asm volatile("mma.sync.aligned.m16n8k16.row.col.f32.bf16.bf16.f32 " \
        "{%0,%1,%2,%3}, {%4,%5,%6,%7}, {%8,%9}, {%0,%1,%2,%3};" \
        : "+f"((d)[0]), "+f"((d)[1]), "+f"((d)[2]), "+f"((d)[3]) \
        : "r"((a)[0]), "r"((a)[1]), "r"((a)[2]), "r"((a)[3]), "r"(b0), "r"(b1))

__device__ __forceinline__ void split_bf16(float x, __nv_bfloat16& h, __nv_bfloat16& l) {
    h = __float2bfloat16_rn(x);
    l = __float2bfloat16_rn(x - __bfloat162float(h));
}
__device__ __forceinline__ void split2(float a, float b, uint32_t& hi, uint32_t& lo) {
    __nv_bfloat16 ha, la, hb, lb;
    split_bf16(a, ha, la); split_bf16(b, hb, lb);
    __nv_bfloat162 H; H.x = ha; H.y = hb;
    __nv_bfloat162 L; L.x = la; L.y = lb;
    hi = *reinterpret_cast<uint32_t*>(&H);
    lo = *reinterpret_cast<uint32_t*>(&L);
}

// ---------------------------------------------------------------------------
// conv_split (hidden/A and Wo)
// ---------------------------------------------------------------------------
__global__ void conv_split(const float4* __restrict__ X, __nv_bfloat162* __restrict__ H,
                           __nv_bfloat162* __restrict__ L)
{
    const size_t i = (size_t)blockIdx.x * blockDim.x + threadIdx.x;
    float4 v = X[i];
    __nv_bfloat16 h0, l0, h1, l1, h2, l2, h3, l3;
    split_bf16(v.x, h0, l0); split_bf16(v.y, h1, l1);
    split_bf16(v.z, h2, l2); split_bf16(v.w, h3, l3);
    __nv_bfloat162 a, b, c, d;
    a.x = h0; a.y = h1;  b.x = h2; b.y = h3;
    c.x = l0; c.y = l1;  d.x = l2; d.y = l3;
    H[2 * i] = a; H[2 * i + 1] = b;
    L[2 * i] = c; L[2 * i + 1] = d;
}

// ---------------------------------------------------------------------------
// convB_qkv: permuted QKV weight conversion (rope pairs adjacent)
// ---------------------------------------------------------------------------
__global__ void convB_qkv(const float* __restrict__ W)
{
    const size_t idx = (size_t)blockIdx.x * 256 + threadIdx.x;
    const int k = (int)(idx >> 12);
    const int c = (int)((idx & 4095) << 1);
    const int head = c >> 8;
    const int dn   = c & 255;
    float w1, w2;
    const float* rowp = W + (size_t)k * QKV_N;
    if (head < NH + NKV) {
        const int j = dn >> 1;
        w1 = rowp[head * 256 + j];
        w2 = rowp[head * 256 + j + 128];
    } else {
        w1 = rowp[c];
        w2 = rowp[c + 1];
    }
    uint32_t hi, lo;
    split2(w1, w2, hi, lo);
    const size_t o = (size_t)k * QKV_N + c;
    *reinterpret_cast<uint32_t*>(&g_Bh[o]) = hi;
    *reinterpret_cast<uint32_t*>(&g_Bl[o]) = lo;
}

// ---------------------------------------------------------------------------
// Fused epilogue store for the QKV GEMM (rope in-register, split to planes)
// ---------------------------------------------------------------------------
__device__ __forceinline__ void qkv_store(int row, int col, float x1, float x2,
                                          const float* __restrict__ fcos,
                                          const float* __restrict__ fsin)
{
    const int head = col >> 8;
    const int dn   = col & 255;
    uint32_t hi, lo;
    if (head < NH + NKV) {
        const int j = dn >> 1;
        const float cv = fcos[(size_t)row * 128 + j];
        const float sv = fsin[(size_t)row * 128 + j];
        float y1 = x1 * cv - x2 * sv;
        float y2 = x1 * sv + x2 * cv;
        if (head < NH) {
            y1 *= SCALING; y2 *= SCALING;
            split2(y1, y2, hi, lo);
            const size_t o = ((size_t)head * S_LEN + row) * HD + dn;
            *reinterpret_cast<uint32_t*>(&g_Qh[o]) = hi;
            *reinterpret_cast<uint32_t*>(&g_Ql[o]) = lo;
        } else {
            split2(y1, y2, hi, lo);
            const size_t o = ((size_t)(head - NH) * S_LEN + row) * HD + dn;
            *reinterpret_cast<uint32_t*>(&g_Kh[o]) = hi;
            *reinterpret_cast<uint32_t*>(&g_Kl[o]) = lo;
        }
    } else {
        split2(x1, x2, hi, lo);
        const size_t o = ((size_t)(head - NH - NKV) * S_LEN + row) * HD + dn;
        *reinterpret_cast<uint32_t*>(&g_Vh[o]) = hi;
        *reinterpret_cast<uint32_t*>(&g_Vl[o]) = lo;
    }
}

// ---------------------------------------------------------------------------
// HMMA split-bf16 GEMM (R12/R13 proven single-barrier 3-stage pipeline)
// ---------------------------------------------------------------------------
#define BM   128
#define BN   128
#define BK   32
#define LDA  40
#define LDB  136
#define TILE_A_B (128 * LDA * 2)
#define TILE_B_B (32 * LDB * 2)
#define OFF_AH   0
#define OFF_AL   (TILE_A_B)
#define OFF_BH   (2 * TILE_A_B)
#define OFF_BL   (2 * TILE_A_B + TILE_B_B)
#define STAGE_B  (2 * TILE_A_B + 2 * TILE_B_B)
#define NSTG 3

template <bool FUSE_ROPE>
__global__ void __launch_bounds__(256, 2)
gemm_mma(const __nv_bfloat16* __restrict__ Ah, const __nv_bfloat16* __restrict__ Al,
         const __nv_bfloat16* __restrict__ Bh, const __nv_bfloat16* __restrict__ Bl,
         float* __restrict__ C, int N, int K,
         const float* __restrict__ fcos, const float* __restrict__ fsin)
{
    extern __shared__ char smbuf[];
    const uint32_t sb = smem_u32(smbuf);

    const int tid  = threadIdx.x;
    const int lane = tid & 31;
    const int wid  = tid >> 5;
    const int wm   = (wid & 3) * 32;
    const int wn   = (wid >> 2) * 64;
    const int nb   = blockIdx.x, mbk = blockIdx.y;
    const int m0   = mbk * BM, n0 = nb * BN;
    const int KT   = K / BK;

    const int ar = tid >> 1, ac = (tid & 1) * 16;
    const int br = tid >> 3, bc = (tid & 7) * 16;

    const __nv_bfloat16* gAh = Ah + (size_t)(m0 + ar) * K + ac;
    const __nv_bfloat16* gAl = Al + (size_t)(m0 + ar) * K + ac;
    const __nv_bfloat16* gBh = Bh + (size_t)br * N + n0 + bc;
    const __nv_bfloat16* gBl = Bl + (size_t)br * N + n0 + bc;

    auto load_stage = [&](int s, int c) {
        const uint32_t st = sb + s * STAGE_B;
        const size_t ka = (size_t)c * BK;
        const uint32_t sa = st + (ar * LDA + ac) * 2;
        CP_ASYNC16(sa + OFF_AH,      gAh + ka);
        CP_ASYNC16(sa + OFF_AH + 16, gAh + ka + 8);
        CP_ASYNC16(sa + OFF_AL,      gAl + ka);
        CP_ASYNC16(sa + OFF_AL + 16, gAl + ka + 8);
        const uint32_t sbm = st + (br * LDB + bc) * 2;
        const size_t kb = (size_t)c * BK * N;
        CP_ASYNC16(sbm + OFF_BH,      gBh + kb);
        CP_ASYNC16(sbm + OFF_BH + 16, gBh + kb + 8);
        CP_ASYNC16(sbm + OFF_BL,      gBl + kb);
        CP_ASYNC16(sbm + OFF_BL + 16, gBl + kb + 8);
    };

    load_stage(0, 0); CP_COMMIT();
    load_stage(1, 1); CP_COMMIT();

    float d[2][8][4];
    #pragma unroll
    for (int i = 0; i < 2; i++)
        #pragma unroll
        for (int j = 0; j < 8; j++)
            #pragma unroll
            for (int r = 0; r < 4; r++) d[i][j][r] = 0.f;

    const int lrow = lane & 15;
    const int lcol = (lane >> 4) * 8;

    for (int c = 0; c < KT; c++) {
        CP_WAIT1();
        __syncthreads();
        const int c2 = c + 2;
        if (c2 < KT) load_stage(c2 % NSTG, c2);
        CP_COMMIT();

        const uint32_t st = sb + (c % NSTG) * STAGE_B;

        #pragma unroll
        for (int ks = 0; ks < 2; ks++) {
            uint32_t ah[2][4], al[2][4];
            #pragma unroll
            for (int mb = 0; mb < 2; mb++) {
                const uint32_t aoff = st + ((wm + mb * 16 + lrow) * LDA + ks * 16 + lcol) * 2;
                LDSM_X4(ah[mb][0], ah[mb][1], ah[mb][2], ah[mb][3], aoff + OFF_AH);
                LDSM_X4(al[mb][0], al[mb][1], al[mb][2], al[mb][3], aoff + OFF_AL);
            }
            uint32_t bh[4][4], bl[4][4];
            #pragma unroll
            for (int ng = 0; ng < 4; ng++) {
                const uint32_t boff = st + ((ks * 16 + lrow) * LDB + wn + ng * 16 + lcol) * 2;
                LDSM_X4T(bh[ng][0], bh[ng][1], bh[ng][2], bh[ng][3], boff + OFF_BH);
                LDSM_X4T(bl[ng][0], bl[ng][1], bl[ng][2], bl[ng][3], boff + OFF_BL);
            }
            #pragma unroll
            for (int mb = 0; mb < 2; mb++) {
                #pragma unroll
                for (int ng = 0; ng < 4; ng++) {
                    MMA_BF16(d[mb][ng * 2 + 0], ah[mb], bh[ng][0], bh[ng][1]);
                    MMA_BF16(d[mb][ng * 2 + 1], ah[mb], bh[ng][2], bh[ng][3]);
                    MMA_BF16(d[mb][ng * 2 + 0], ah[mb], bl[ng][0], bl[ng][1]);
                    MMA_BF16(d[mb][ng * 2 + 1], ah[mb], bl[ng][2], bl[ng][3]);
                    MMA_BF16(d[mb][ng * 2 + 0], al[mb], bh[ng][0], bh[ng][1]);
                    MMA_BF16(d[mb][ng * 2 + 1], al[mb], bh[ng][2], bh[ng][3]);
                }
            }
        }
    }

    #pragma unroll
    for (int mb = 0; mb < 2; mb++) {
        const int row = m0 + wm + mb * 16 + (lane >> 2);
        #pragma unroll
        for (int nb8 = 0; nb8 < 8; nb8++) {
            const int col = n0 + wn + nb8 * 8 + (lane & 3) * 2;
            if (FUSE_ROPE) {
                qkv_store(row,     col, d[mb][nb8][0], d[mb][nb8][1], fcos, fsin);
                qkv_store(row + 8, col, d[mb][nb8][2], d[mb][nb8][3], fcos, fsin);
            } else {
                float2 v0 = make_float2(d[mb][nb8][0], d[mb][nb8][1]);
                float2 v1 = make_float2(d[mb][nb8][2], d[mb][nb8][3]);
                *reinterpret_cast<float2*>(C + (size_t)row * N + col) = v0;
                *reinterpret_cast<float2*>(C + (size_t)(row + 8) * N + col) = v1;
            }
        }
    }
}

// ---------------------------------------------------------------------------
// Tensor-core flash attention, 8 warps (R13 structure) with QK dependency
// chains split 3-way (sf1=qh*kh, sf2=qh*kl, sf3=ql*kh; summed post-loop).
// ---------------------------------------------------------------------------
#define SROWB 528
#define QPLANE (64 * SROWB)
#define KVPLANE (32 * SROWB)
#define KVSTAGE (4 * KVPLANE)
#define ATTN_SMEM (2 * QPLANE + 2 * KVSTAGE + 256)

__global__ void __launch_bounds__(256, 1) attn_mma_kernel()
{
    extern __shared__ char smv[];
    const uint32_t sb = smem_u32(smv);
    const uint32_t QH = sb, QL = sb + QPLANE, ST0 = sb + 2 * QPLANE;
    float* sSum = reinterpret_cast<float*>(smv + 2 * QPLANE + 2 * KVSTAGE);

    const int tid  = threadIdx.x;
    const int lane = tid & 31;
    const int wid  = tid >> 5;
    const int wq   = wid >> 1;
    const int kg   = wid & 1;
    const int q0   = blockIdx.x * 64;
    const int h    = blockIdx.y;
    const int kvh  = h >> 1;

    const int lrow  = lane & 15;
    const int lcolb = (lane >> 4) * 16;
    const int g     = lane >> 2;
    const int t2    = (lane & 3) * 2;

    if (tid < 64) sSum[tid] = 0.f;

    const __nv_bfloat16* pQh = g_Qh + ((size_t)h * S_LEN + q0) * HD;
    const __nv_bfloat16* pQl = g_Ql + ((size_t)h * S_LEN + q0) * HD;
    const __nv_bfloat16* bKh = g_Kh + (size_t)kvh * S_LEN * HD;
    const __nv_bfloat16* bKl = g_Kl + (size_t)kvh * S_LEN * HD;
    const __nv_bfloat16* bVh = g_Vh + (size_t)kvh * S_LEN * HD;
    const __nv_bfloat16* bVl = g_Vl + (size_t)kvh * S_LEN * HD;

    for (int i = tid; i < 64 * 32; i += 256) {
        const int r = i >> 5, ch = i & 31;
        const uint32_t o = (uint32_t)r * SROWB + ch * 16;
        const size_t go = (size_t)r * HD + ch * 8;
        CP_ASYNC16(QH + o, pQh + go);
        CP_ASYNC16(QL + o, pQl + go);
    }

    auto load_kv = [&](int s, int kb) {
        const uint32_t base = ST0 + s * KVSTAGE;
        for (int i = tid; i < 32 * 32; i += 256) {
            const int r = i >> 5, ch = i & 31;
            const uint32_t o = (uint32_t)r * SROWB + ch * 16;
            const size_t go = (size_t)(kb + r) * HD + ch * 8;
            CP_ASYNC16(base + o,               bKh + go);
            CP_ASYNC16(base + KVPLANE + o,     bKl + go);
            CP_ASYNC16(base + 2 * KVPLANE + o, bVh + go);
            CP_ASYNC16(base + 3 * KVPLANE + o, bVl + go);
        }
    };

    const int klo = (q0 - (WIN - 1)) > 0 ? (q0 - (WIN - 1)) : 0;
    const int kb0 = klo & ~31;
    const int nch = (q0 + 64 - kb0) >> 5;

    load_kv(0, kb0); CP_COMMIT();
    if (nch > 1) load_kv(1, kb0 + 32);
    CP_COMMIT();

    float o[32][4];
    #pragma unroll
    for (int i = 0; i < 32; i++)
        #pragma unroll
        for (int r = 0; r < 4; r++) o[i][r] = 0.f;
    float rs0 = 0.f, rs1 = 0.f;
    const int qrow0 = q0 + wq * 16 + g;

    for (int ic = 0; ic < nch; ic++) {
        const int kb = kb0 + ic * 32;
        CP_WAIT1();
        __syncthreads();
        const uint32_t st = ST0 + (ic & 1) * KVSTAGE;

        // ---- S = Q K^T, 3 independent accumulation chains ----
        float sf1[2][4], sf2[2][4], sf3[2][4];
        #pragma unroll
        for (int t = 0; t < 2; t++)
            #pragma unroll
            for (int r = 0; r < 4; r++) { sf1[t][r] = 0.f; sf2[t][r] = 0.f; sf3[t][r] = 0.f; }

        #pragma unroll
        for (int dc = 0; dc < 16; dc++) {
            const uint32_t qa = QH + (uint32_t)(wq * 16 + lrow) * SROWB + dc * 32 + lcolb;
            uint32_t ah[4], al[4];
            LDSM_X4(ah[0], ah[1], ah[2], ah[3], qa);
            LDSM_X4(al[0], al[1], al[2], al[3], qa + QPLANE);
            const uint32_t ka = st + (uint32_t)(kg * 16 + lrow) * SROWB + dc * 32 + lcolb;
            uint32_t bh[4], bl[4];
            LDSM_X4(bh[0], bh[1], bh[2], bh[3], ka);
            LDSM_X4(bl[0], bl[1], bl[2], bl[3], ka + KVPLANE);
            MMA_BF16(sf1[0], ah, bh[0], bh[2]);
            MMA_BF16(sf1[1], ah, bh[1], bh[3]);
            MMA_BF16(sf2[0], ah, bl[0], bl[2]);
            MMA_BF16(sf2[1], ah, bl[1], bl[3]);
            MMA_BF16(sf3[0], al, bh[0], bh[2]);
            MMA_BF16(sf3[1], al, bh[1], bh[3]);
        }

        // ---- combine chains + softcap + mask + exp(t-50) ----
        uint32_t ph[2][2], pl[2][2];
        #pragma unroll
        for (int t = 0; t < 2; t++) {
            const int kcol = kb + kg * 16 + t * 8 + t2;
            float pv[4];
            #pragma unroll
            for (int r = 0; r < 4; r++) {
                const float s = sf1[t][r] + sf2[t][r] + sf3[t][r];
                const int q = qrow0 + ((r >= 2) ? 8 : 0);
                const int k = kcol + (r & 1);
                const float u = __expf(0.04f * s);
                const float p = __expf(__fdividef(-100.f, u + 1.f));
                pv[r] = (k <= q && (q - k) < WIN) ? p : 0.f;
            }
            rs0 += pv[0] + pv[1];
            rs1 += pv[2] + pv[3];
            split2(pv[0], pv[1], ph[t][0], pl[t][0]);
            split2(pv[2], pv[3], ph[t][1], pl[t][1]);
        }

        // ---- O += P V over this warp's 16-k half ----
        uint32_t pah[4] = { ph[0][0], ph[0][1], ph[1][0], ph[1][1] };
        uint32_t pal[4] = { pl[0][0], pl[0][1], pl[1][0], pl[1][1] };
        #pragma unroll
        for (int dc = 0; dc < 16; dc++) {
            const uint32_t va = st + 2 * KVPLANE +
                (uint32_t)(kg * 16 + lrow) * SROWB + dc * 32 + lcolb;
            uint32_t vh[4], vl[4];
            LDSM_X4T(vh[0], vh[1], vh[2], vh[3], va);
            LDSM_X4T(vl[0], vl[1], vl[2], vl[3], va + KVPLANE);
            MMA_BF16(o[dc * 2 + 0], pah, vh[0], vh[1]);
            MMA_BF16(o[dc * 2 + 1], pah, vh[2], vh[3]);
            MMA_BF16(o[dc * 2 + 0], pah, vl[0], vl[1]);
            MMA_BF16(o[dc * 2 + 1], pah, vl[2], vl[3]);
            MMA_BF16(o[dc * 2 + 0], pal, vh[0], vh[1]);
            MMA_BF16(o[dc * 2 + 1], pal, vh[2], vh[3]);
        }
        __syncthreads();
        if (ic + 2 < nch) load_kv(ic & 1, kb + 64);
        CP_COMMIT();
    }

    rs0 += __shfl_xor_sync(0xFFFFFFFFu, rs0, 1);
    rs0 += __shfl_xor_sync(0xFFFFFFFFu, rs0, 2);
    rs1 += __shfl_xor_sync(0xFFFFFFFFu, rs1, 1);
    rs1 += __shfl_xor_sync(0xFFFFFFFFu, rs1, 2);
    if ((lane & 3) == 0) {
        atomicAdd(&sSum[wq * 16 + g], rs0);
        atomicAdd(&sSum[wq * 16 + g + 8], rs1);
    }

    float* red = reinterpret_cast<float*>(smv + 2 * QPLANE + (nch & 1) * KVSTAGE);
    if (kg == 1) {
        #pragma unroll
        for (int t = 0; t < 32; t++) {
            const int c  = (t >> 1) * 16 + (t & 1) * 8 + t2;
            const int r0 = wq * 16 + g;
            *reinterpret_cast<float2*>(&red[(size_t)r0 * 256 + c])       = make_float2(o[t][0], o[t][1]);
            *reinterpret_cast<float2*>(&red[(size_t)(r0 + 8) * 256 + c]) = make_float2(o[t][2], o[t][3]);
        }
    }
    __syncthreads();
    if (kg == 0) {
        const float i0 = 1.0f / sSum[wq * 16 + g];
        const float i1 = 1.0f / sSum[wq * 16 + g + 8];
        const int row0 = q0 + wq * 16 + g;
        const int rl   = wq * 16 + g;
        #pragma unroll
        for (int t = 0; t < 32; t++) {
            const int c   = (t >> 1) * 16 + (t & 1) * 8 + t2;
            const int col = h * HD + c;
            float2 p0 = *reinterpret_cast<float2*>(&red[(size_t)rl * 256 + c]);
            float2 p1 = *reinterpret_cast<float2*>(&red[(size_t)(rl + 8) * 256 + c]);
            uint32_t hi, lo;
            split2((o[t][0] + p0.x) * i0, (o[t][1] + p0.y) * i0, hi, lo);
            *reinterpret_cast<uint32_t*>(&g_Ah[(size_t)row0 * ATTN_N + col]) = hi;
            *reinterpret_cast<uint32_t*>(&g_Al[(size_t)row0 * ATTN_N + col]) = lo;
            split2((o[t][2] + p1.x) * i1, (o[t][3] + p1.y) * i1, hi, lo);
            *reinterpret_cast<uint32_t*>(&g_Ah[(size_t)(row0 + 8) * ATTN_N + col]) = hi;
            *reinterpret_cast<uint32_t*>(&g_Al[(size_t)(row0 + 8) * ATTN_N + col]) = lo;
        }
    }
}

// ---------------------------------------------------------------------------
extern "C" void kernel_launch(void* const* d_in, const int* in_sizes, int n_in,
                              void* d_out, int out_size)
{
    const float* hidden = (const float*)d_in[0];
    const float* Wqkv   = (const float*)d_in[1];
    const float* Wo     = (const float*)d_in[2];
    const float* fcos   = (const float*)d_in[3];
    const float* fsin   = (const float*)d_in[4];
    float* out = (float*)d_out;

    __nv_bfloat16 *Ah, *Al, *Bh, *Bl;
    cudaGetSymbolAddress((void**)&Ah, g_Ah);
    cudaGetSymbolAddress((void**)&Al, g_Al);
    cudaGetSymbolAddress((void**)&Bh, g_Bh);
    cudaGetSymbolAddress((void**)&Bl, g_Bl);

    const int gemm_smem = NSTG * STAGE_B;                 // 113664
    cudaFuncSetAttribute(gemm_mma<true>,  cudaFuncAttributeMaxDynamicSharedMemorySize, gemm_smem);
    cudaFuncSetAttribute(gemm_mma<false>, cudaFuncAttributeMaxDynamicSharedMemorySize, gemm_smem);
    cudaFuncSetAttribute(attn_mma_kernel, cudaFuncAttributeMaxDynamicSharedMemorySize, ATTN_SMEM);

    conv_split<<<(S_LEN * HID_DIM / 4) / 256, 256>>>(
        (const float4*)hidden, (__nv_bfloat162*)Ah, (__nv_bfloat162*)Al);
    convB_qkv<<<(HID_DIM * (QKV_N / 2)) / 256, 256>>>(Wqkv);

    gemm_mma<true><<<dim3(QKV_N / BN, S_LEN / BM), 256, gemm_smem>>>(
        Ah, Al, Bh, Bl, nullptr, QKV_N, HID_DIM, fcos, fsin);

    attn_mma_kernel<<<dim3(S_LEN / 64, NH), 256, ATTN_SMEM>>>();

    conv_split<<<((size_t)ATTN_N * HID_DIM / 4) / 256, 256>>>(
        (const float4*)Wo, (__nv_bfloat162*)Bh, (__nv_bfloat162*)Bl);
    gemm_mma<false><<<dim3(HID_DIM / BN, S_LEN / BM), 256, gemm_smem>>>(
        Ah, Al, Bh, Bl, out, HID_DIM, ATTN_N, nullptr, nullptr);
}